// round 12
// baseline (speedup 1.0000x reference)
#include <cuda_runtime.h>
#include <cuda_fp16.h>
#include <math.h>
#include <cstdint>

#define E_TOTAL 160000
#define NNODES  10000
#define EPB     128
#define INV_SQRT3 0.5773502691896258f
#define ALPHA     0.17677669529663687f

// ---- smem float offsets ----
// HS: 128 rows x 136 halves (emb->h tile, fp16) = [0, 8704)
#define WS_OFF   8704     // 2 x 16KB W fragment buffers (fp16)
#define CS1_OFF  16896    // [128][17] f32: INV_SQRT3*(v . sh1)
#define SV_OFF   19072    // [128][17] f32: raw s
#define VV_OFF   21248    // [128][49] f32: raw v (3u+m)
#define SH_OFF   27520    // [128][4]  f32: edge_sh
#define DST_OFF  28032    // [128] int
#define TOTF     28160
#define SMEM_BYTES (TOTF * 4)   // 112640 B -> 2 CTAs/SM

// paired-kt fragment layout (uint4 per lane serves kt=2*ktp and 2*ktp+1)
__device__ __align__(16) __half g_W1F[16384];        // 32KB
__device__ __align__(16) __half g_W2F[16 * 8192];    // 16 chunks x 16KB
__device__ float g_cnt[NNODES];

__device__ __forceinline__ float gelu_exact(float x) {
    return 0.5f * x * (1.0f + erff(x * 0.7071067811865476f));
}
__device__ __forceinline__ void red2(float* p, float a, float b) {
    asm volatile("red.global.add.v2.f32 [%0], {%1, %2};"
                 :: "l"(p), "f"(a), "f"(b) : "memory");
}
__device__ __forceinline__ void mma16(float* c, const unsigned* a,
                                      unsigned b0, unsigned b1) {
    asm("mma.sync.aligned.m16n8k16.row.col.f32.f16.f16.f32 "
        "{%0,%1,%2,%3}, {%4,%5,%6,%7}, {%8,%9}, {%0,%1,%2,%3};"
        : "+f"(c[0]), "+f"(c[1]), "+f"(c[2]), "+f"(c[3])
        : "r"(a[0]), "r"(a[1]), "r"(a[2]), "r"(a[3]), "r"(b0), "r"(b1));
}
__device__ __forceinline__ void cpasync16(uint32_t s, const void* g) {
    asm volatile("cp.async.cg.shared.global [%0], [%1], 16;" :: "r"(s), "l"(g));
}
__device__ __forceinline__ void cpcommit() {
    asm volatile("cp.async.commit_group;" ::: "memory");
}
__device__ __forceinline__ void cpwait0() {
    asm volatile("cp.async.wait_group 0;" ::: "memory");
}

// ---------------- prep: fp16 weights in paired-kt fragment order ---------------
__global__ void k_prep(const float* __restrict__ W1, const float* __restrict__ W2,
                       float4* __restrict__ out4) {
    int i = blockIdx.x * 256 + threadIdx.x;
    if (i < NNODES * 16) out4[i] = make_float4(0.f, 0.f, 0.f, 0.f);
    if (i < NNODES) g_cnt[i] = 0.0f;
    if (i < 16384) {
        int hh = i & 1, w = (i >> 1) & 3, lane = (i >> 3) & 31;
        int ktp = (i >> 8) & 3, nt = (i >> 10) & 7, h = (i >> 13) & 1;
        int kt = 2 * ktp + (w >> 1), pair = w & 1;
        int q = lane & 3, g = lane >> 2;
        int k = kt * 16 + pair * 8 + 2 * q + hh, n = h * 64 + nt * 8 + g;
        g_W1F[i] = __float2half_rn(W1[k * 128 + n]);
    } else if (i < 16384 + 131072) {
        int j = i - 16384;
        int hh = j & 1, w = (j >> 1) & 3, lane = (j >> 3) & 31;
        int ktp = (j >> 8) & 3, nt = (j >> 10) & 7, c = (j >> 13) & 15;
        int kt = 2 * ktp + (w >> 1), pair = w & 1;
        int q = lane & 3, g = lane >> 2;
        int k = kt * 16 + pair * 8 + 2 * q + hh, col = c * 64 + nt * 8 + g;
        g_W2F[j] = __float2half_rn(W2[k * 1024 + col]);
    }
}

__global__ void k_norm(float4* __restrict__ out4) {
    int i = blockIdx.x * blockDim.x + threadIdx.x;
    if (i < NNODES * 16) {
        float inv = 1.0f / fmaxf(g_cnt[i >> 4], 1.0f);
        float4 o = out4[i];
        o.x *= inv; o.y *= inv; o.z *= inv; o.w *= inv;
        out4[i] = o;
    }
}

// ---------------- fused kernel: 4 warps, 32 rows/warp ----------------
__global__ void __launch_bounds__(128, 2)
k_fused(const float* __restrict__ xfeat, const float* __restrict__ esh,
        const float* __restrict__ emb, const float* __restrict__ b1,
        const float* __restrict__ b2, const int* __restrict__ src,
        const int* __restrict__ dstp, float* __restrict__ out) {
    extern __shared__ float sm[];
    __half* hs = (__half*)sm;                    // 128 x 136 halves (272B rows)
    char* wsc = (char*)(sm + WS_OFF);
    const uint32_t wsb = (uint32_t)__cvta_generic_to_shared(wsc);
    const int tid = threadIdx.x, wid = tid >> 5, lane = tid & 31;
    const int qq = lane & 3, gg = lane >> 2;
    const int eBase = blockIdx.x * EPB;
    int r[4];
    r[0] = 32 * wid + gg; r[1] = r[0] + 8; r[2] = r[0] + 16; r[3] = r[0] + 24;

    // ---- stage emb tile as fp16 ----
#pragma unroll
    for (int it = 0; it < 32; it++) {
        int qi = it * 128 + tid;
        int rr = qi >> 5, c4 = qi & 31;
        float4 v = *(const float4*)(emb + (size_t)(eBase + rr) * 128 + 4 * c4);
        __half2 p0 = __floats2half2_rn(v.x, v.y);
        __half2 p1 = __floats2half2_rn(v.z, v.w);
        uint2 pk = {*(unsigned*)&p0, *(unsigned*)&p1};
        *(uint2*)((char*)hs + rr * 272 + 8 * c4) = pk;
    }
    // ---- stage W1F (32KB) via cp.async ----
#pragma unroll
    for (int it = 0; it < 16; it++)
        cpasync16(wsb + (it * 128 + tid) * 16, (const char*)g_W1F + (it * 128 + tid) * 16);
    cpcommit();

    // ---- per-edge TP coefficients (1 thread / edge; warp-local rows) ----
    {
        int e = tid, ge = eBase + e;
        int si = __ldg(src + ge);
        const float* x = xfeat + (size_t)si * 64;
        float4 shv = *(const float4*)(esh + (size_t)ge * 4);
        float s1x = shv.y, s1y = shv.z, s1z = shv.w;
        float sv[16];
#pragma unroll
        for (int p = 0; p < 4; p++) {
            float4 t = *(const float4*)(x + 4 * p);
            sv[4*p] = t.x; sv[4*p+1] = t.y; sv[4*p+2] = t.z; sv[4*p+3] = t.w;
        }
        float vv[48];
#pragma unroll
        for (int p = 0; p < 12; p++) {
            float4 t = *(const float4*)(x + 16 + 4 * p);
            vv[4*p] = t.x; vv[4*p+1] = t.y; vv[4*p+2] = t.z; vv[4*p+3] = t.w;
        }
#pragma unroll
        for (int u = 0; u < 16; u++) {
            float v0 = vv[3*u], v1 = vv[3*u+1], v2 = vv[3*u+2];
            sm[SV_OFF + e * 17 + u] = sv[u];
            sm[CS1_OFF + e * 17 + u] = INV_SQRT3 * (v0 * s1x + v1 * s1y + v2 * s1z);
            sm[VV_OFF + e * 49 + 3 * u + 0] = v0;
            sm[VV_OFF + e * 49 + 3 * u + 1] = v1;
            sm[VV_OFF + e * 49 + 3 * u + 2] = v2;
        }
        *(float4*)(sm + SH_OFF + e * 4) = shv;
        ((int*)(sm + DST_OFF))[e] = __ldg(dstp + ge);
    }
    cpwait0();
    __syncthreads();

    // ---- A fragments: 2 row-tiles per warp ----
    unsigned a[8][8];
#pragma unroll
    for (int kt = 0; kt < 8; kt++)
#pragma unroll
        for (int tl = 0; tl < 2; tl++) {
            a[kt][4*tl+0] = *(const unsigned*)((char*)hs + r[2*tl]   * 272 + kt * 32 + 4 * qq);
            a[kt][4*tl+1] = *(const unsigned*)((char*)hs + r[2*tl+1] * 272 + kt * 32 + 4 * qq);
            a[kt][4*tl+2] = *(const unsigned*)((char*)hs + r[2*tl]   * 272 + kt * 32 + 4 * qq + 16);
            a[kt][4*tl+3] = *(const unsigned*)((char*)hs + r[2*tl+1] * 272 + kt * 32 + 4 * qq + 16);
        }

    // ---- GEMM1: 2 col-halves x 2 row-tiles, paired-kt B, gelu -> h ----
#pragma unroll
    for (int h = 0; h < 2; h++) {
        const uint4* wb = (const uint4*)(wsc + h * 16384);
#pragma unroll
        for (int tl = 0; tl < 2; tl++) {
            float acc[8][4];
#pragma unroll
            for (int nt = 0; nt < 8; nt++) {
                float2 bb = *(const float2*)(b1 + h * 64 + nt * 8 + 2 * qq);
                acc[nt][0] = bb.x; acc[nt][1] = bb.y;
                acc[nt][2] = bb.x; acc[nt][3] = bb.y;
            }
#pragma unroll
            for (int ktp = 0; ktp < 4; ktp++)
#pragma unroll
                for (int nt = 0; nt < 8; nt++) {
                    uint4 b = wb[(nt * 4 + ktp) * 32 + lane];
                    mma16(acc[nt], &a[2*ktp][4*tl],     b.x, b.y);
                    mma16(acc[nt], &a[2*ktp+1][4*tl],   b.z, b.w);
                }
#pragma unroll
            for (int nt = 0; nt < 8; nt++) {
                int col = h * 64 + nt * 8 + 2 * qq;
                __half2 h0 = __floats2half2_rn(gelu_exact(acc[nt][0]), gelu_exact(acc[nt][1]));
                __half2 h1 = __floats2half2_rn(gelu_exact(acc[nt][2]), gelu_exact(acc[nt][3]));
                *(__half2*)((char*)hs + r[2*tl]   * 272 + col * 2) = h0;
                *(__half2*)((char*)hs + r[2*tl+1] * 272 + col * 2) = h1;
            }
        }
    }
    __syncwarp();
    // reload A fragments = h
#pragma unroll
    for (int kt = 0; kt < 8; kt++)
#pragma unroll
        for (int tl = 0; tl < 2; tl++) {
            a[kt][4*tl+0] = *(const unsigned*)((char*)hs + r[2*tl]   * 272 + kt * 32 + 4 * qq);
            a[kt][4*tl+1] = *(const unsigned*)((char*)hs + r[2*tl+1] * 272 + kt * 32 + 4 * qq);
            a[kt][4*tl+2] = *(const unsigned*)((char*)hs + r[2*tl]   * 272 + kt * 32 + 4 * qq + 16);
            a[kt][4*tl+3] = *(const unsigned*)((char*)hs + r[2*tl+1] * 272 + kt * 32 + 4 * qq + 16);
        }
    __syncthreads();   // all warps done with W1F in ws

    float sh0e[4];
#pragma unroll
    for (int ei = 0; ei < 4; ei++) sh0e[ei] = sm[SH_OFF + r[ei] * 4];

    // ---- stage W2 chunk 0 into buf 0 ----
#pragma unroll
    for (int it = 0; it < 8; it++)
        cpasync16(wsb + (it * 128 + tid) * 16, (const char*)g_W2F + (it * 128 + tid) * 16);
    cpcommit();
    cpwait0();
    __syncthreads();

    float r0a[4][4], r2a[4][4], r3a[4][4][3];
#pragma unroll
    for (int ei = 0; ei < 4; ei++)
#pragma unroll
        for (int s = 0; s < 4; s++) {
            r0a[ei][s] = 0.0f; r2a[ei][s] = 0.0f;
            r3a[ei][s][0] = 0.0f; r3a[ei][s][1] = 0.0f; r3a[ei][s][2] = 0.0f;
        }

#pragma unroll 1
    for (int c = 0; c < 16; c++) {
        if (c < 15) {   // prefetch next chunk into other buffer
#pragma unroll
            for (int it = 0; it < 8; it++)
                cpasync16(wsb + ((c + 1) & 1) * 16384 + (it * 128 + tid) * 16,
                          (const char*)g_W2F + (c + 1) * 16384 + (it * 128 + tid) * 16);
            cpcommit();
        }
        const uint4* wb = (const uint4*)(wsc + (c & 1) * 16384);
        const int t = c >> 2, g4 = c & 3;

        // quarters: q4 covers nt = 2*q4, 2*q4+1  ->  single u = 4*g4 + q4
#pragma unroll
        for (int q4 = 0; q4 < 4; q4++) {
            float acc[2][2][4];
#pragma unroll
            for (int ntl = 0; ntl < 2; ntl++) {
                float2 bb = *(const float2*)(b2 + c * 64 + (2*q4 + ntl) * 8 + 2 * qq);
#pragma unroll
                for (int tl = 0; tl < 2; tl++) {
                    acc[ntl][tl][0] = bb.x; acc[ntl][tl][1] = bb.y;
                    acc[ntl][tl][2] = bb.x; acc[ntl][tl][3] = bb.y;
                }
            }
#pragma unroll
            for (int ktp = 0; ktp < 4; ktp++)
#pragma unroll
                for (int ntl = 0; ntl < 2; ntl++) {
                    uint4 b = wb[((2*q4 + ntl) * 4 + ktp) * 32 + lane];
                    mma16(acc[ntl][0], &a[2*ktp][0],   b.x, b.y);
                    mma16(acc[ntl][0], &a[2*ktp+1][0], b.z, b.w);
                    mma16(acc[ntl][1], &a[2*ktp][4],   b.x, b.y);
                    mma16(acc[ntl][1], &a[2*ktp+1][4], b.z, b.w);
                }

            const int u = 4 * g4 + q4;
            if (t <= 2) {
                float cc[4];
#pragma unroll
                for (int ei = 0; ei < 4; ei++) {
                    if (t == 0)      cc[ei] = sh0e[ei] * sm[SV_OFF + r[ei] * 17 + u];
                    else if (t == 1) cc[ei] = sm[CS1_OFF + r[ei] * 17 + u];
                    else             cc[ei] = sm[SV_OFF + r[ei] * 17 + u];
                }
                float (*ra)[4] = (t == 2) ? r2a : r0a;
#pragma unroll
                for (int ntl = 0; ntl < 2; ntl++)
#pragma unroll
                    for (int tl = 0; tl < 2; tl++) {
                        ra[2*tl+0][2*ntl]   = fmaf(cc[2*tl+0], acc[ntl][tl][0], ra[2*tl+0][2*ntl]);
                        ra[2*tl+0][2*ntl+1] = fmaf(cc[2*tl+0], acc[ntl][tl][1], ra[2*tl+0][2*ntl+1]);
                        ra[2*tl+1][2*ntl]   = fmaf(cc[2*tl+1], acc[ntl][tl][2], ra[2*tl+1][2*ntl]);
                        ra[2*tl+1][2*ntl+1] = fmaf(cc[2*tl+1], acc[ntl][tl][3], ra[2*tl+1][2*ntl+1]);
                    }
            } else {
                float vc[4][3];
#pragma unroll
                for (int ei = 0; ei < 4; ei++)
#pragma unroll
                    for (int m = 0; m < 3; m++)
                        vc[ei][m] = sm[VV_OFF + r[ei] * 49 + 3 * u + m];
#pragma unroll
                for (int ntl = 0; ntl < 2; ntl++)
#pragma unroll
                    for (int tl = 0; tl < 2; tl++) {
                        float d0 = sh0e[2*tl+0] * acc[ntl][tl][0];
                        float d1 = sh0e[2*tl+0] * acc[ntl][tl][1];
                        float d2 = sh0e[2*tl+1] * acc[ntl][tl][2];
                        float d3 = sh0e[2*tl+1] * acc[ntl][tl][3];
#pragma unroll
                        for (int m = 0; m < 3; m++) {
                            r3a[2*tl+0][2*ntl][m]   = fmaf(vc[2*tl+0][m], d0, r3a[2*tl+0][2*ntl][m]);
                            r3a[2*tl+0][2*ntl+1][m] = fmaf(vc[2*tl+0][m], d1, r3a[2*tl+0][2*ntl+1][m]);
                            r3a[2*tl+1][2*ntl][m]   = fmaf(vc[2*tl+1][m], d2, r3a[2*tl+1][2*ntl][m]);
                            r3a[2*tl+1][2*ntl+1][m] = fmaf(vc[2*tl+1][m], d3, r3a[2*tl+1][2*ntl+1][m]);
                        }
                    }
            }
        }

        if (c == 7) {   // scatter out0
#pragma unroll
            for (int ei = 0; ei < 4; ei++) {
                int dn = ((int*)(sm + DST_OFF))[r[ei]];
                float* op = out + (size_t)dn * 64;
                red2(op + 2*qq,     ALPHA * r0a[ei][0], ALPHA * r0a[ei][1]);
                red2(op + 2*qq + 8, ALPHA * r0a[ei][2], ALPHA * r0a[ei][3]);
                if (qq == 0) atomicAdd(&g_cnt[dn], 1.0f);
            }
        }
        if (c == 15) {  // scatter out1
#pragma unroll
            for (int ei = 0; ei < 4; ei++) {
                float s1m[3];
#pragma unroll
                for (int m = 0; m < 3; m++) s1m[m] = sm[SH_OFF + r[ei] * 4 + 1 + m];
                int dn = ((int*)(sm + DST_OFF))[r[ei]];
                float* op = out + (size_t)dn * 64 + 16;
                float va[4][3];
#pragma unroll
                for (int s = 0; s < 4; s++)
#pragma unroll
                    for (int m = 0; m < 3; m++)
                        va[s][m] = ALPHA * fmaf(s1m[m], r2a[ei][s], r3a[ei][s][m]);
                red2(op + 6*qq + 0, va[0][0], va[0][1]);
                red2(op + 6*qq + 2, va[0][2], va[1][0]);
                red2(op + 6*qq + 4, va[1][1], va[1][2]);
                red2(op + 6*qq + 24, va[2][0], va[2][1]);
                red2(op + 6*qq + 26, va[2][2], va[3][0]);
                red2(op + 6*qq + 28, va[3][1], va[3][2]);
            }
        }
        cpwait0();
        __syncthreads();
    }
}

// ---------------------------------------------------------------------------
extern "C" void kernel_launch(void* const* d_in, const int* in_sizes, int n_in,
                              void* d_out, int out_size) {
    const float* xfeat = (const float*)d_in[0];
    const float* eshv  = (const float*)d_in[1];
    const float* emb   = (const float*)d_in[2];
    const float* W1    = (const float*)d_in[3];
    const float* b1    = (const float*)d_in[4];
    const float* W2    = (const float*)d_in[5];
    const float* b2    = (const float*)d_in[6];
    const int*   src   = (const int*)d_in[7];
    const int*   dstp  = (const int*)d_in[8];
    float* out = (float*)d_out;

    cudaFuncSetAttribute(k_fused, cudaFuncAttributeMaxDynamicSharedMemorySize, SMEM_BYTES);

    k_prep<<<(NNODES * 16 + 255) / 256, 256>>>(W1, W2, (float4*)out);
    k_fused<<<E_TOTAL / EPB, 128, SMEM_BYTES>>>(xfeat, eshv, emb, b1, b2, src, dstp, out);
    k_norm<<<(NNODES * 16 + 255) / 256, 256>>>((float4*)out);
}

// round 13
// speedup vs baseline: 1.1950x; 1.1950x over previous
#include <cuda_runtime.h>
#include <cuda_fp16.h>
#include <math.h>
#include <cstdint>

#define E_TOTAL 160000
#define NNODES  10000
#define EPB     128
#define INV_SQRT3 0.5773502691896258f
#define ALPHA     0.17677669529663687f

// ---- smem float offsets ----
// HS: 128 rows x 136 halves (emb->h tile, fp16) = [0, 8704)
#define WS_OFF   8704     // 2 x 16KB W fragment buffers (fp16)
#define CS1_OFF  16896    // [128][17] f32: inv*INV_SQRT3*(v . sh1)
#define SV_OFF   19072    // [128][17] f32: inv*s
#define VV_OFF   21248    // [128][49] f32: inv*v (3u+m)
#define SH_OFF   27520    // [128][4]  f32: edge_sh
#define DST_OFF  28032    // [128] int
#define TOTF     28160
#define SMEM_BYTES (TOTF * 4)   // 112640 B -> 2 CTAs/SM

// paired-kt fragment layout (uint4 per lane serves kt=2*ktp and 2*ktp+1):
// half idx = ((((blk*8+nt)*4+ktp)*32+lane)*4 + w)*2 + hh,  kt=2*ktp+(w>>1), pair=w&1
__device__ __align__(16) __half g_W1F[16384];        // 32KB
__device__ __align__(16) __half g_W2F[16 * 8192];    // 16 chunks x 16KB
__device__ float g_cnt[NNODES];

__device__ __forceinline__ float gelu_exact(float x) {
    return 0.5f * x * (1.0f + erff(x * 0.7071067811865476f));
}
__device__ __forceinline__ void red2(float* p, float a, float b) {
    asm volatile("red.global.add.v2.f32 [%0], {%1, %2};"
                 :: "l"(p), "f"(a), "f"(b) : "memory");
}
__device__ __forceinline__ void mma16(float* c, const unsigned* a,
                                      unsigned b0, unsigned b1) {
    asm("mma.sync.aligned.m16n8k16.row.col.f32.f16.f16.f32 "
        "{%0,%1,%2,%3}, {%4,%5,%6,%7}, {%8,%9}, {%0,%1,%2,%3};"
        : "+f"(c[0]), "+f"(c[1]), "+f"(c[2]), "+f"(c[3])
        : "r"(a[0]), "r"(a[1]), "r"(a[2]), "r"(a[3]), "r"(b0), "r"(b1));
}
__device__ __forceinline__ void cpasync16(uint32_t s, const void* g) {
    asm volatile("cp.async.cg.shared.global [%0], [%1], 16;" :: "r"(s), "l"(g));
}
__device__ __forceinline__ void cpcommit() {
    asm volatile("cp.async.commit_group;" ::: "memory");
}
__device__ __forceinline__ void cpwait0() {
    asm volatile("cp.async.wait_group 0;" ::: "memory");
}

// ---------------- prep: zero out+cnt, fp16 weights in paired-kt order ----------
__global__ void k_prep(const float* __restrict__ W1, const float* __restrict__ W2,
                       float4* __restrict__ out4) {
    int i = blockIdx.x * 256 + threadIdx.x;
    if (i < NNODES * 16) out4[i] = make_float4(0.f, 0.f, 0.f, 0.f);
    if (i < NNODES) g_cnt[i] = 0.0f;
    if (i < 16384) {
        int hh = i & 1, w = (i >> 1) & 3, lane = (i >> 3) & 31;
        int ktp = (i >> 8) & 3, nt = (i >> 10) & 7, h = (i >> 13) & 1;
        int kt = 2 * ktp + (w >> 1), pair = w & 1;
        int q = lane & 3, g = lane >> 2;
        int k = kt * 16 + pair * 8 + 2 * q + hh, n = h * 64 + nt * 8 + g;
        g_W1F[i] = __float2half_rn(W1[k * 128 + n]);
    } else if (i < 16384 + 131072) {
        int j = i - 16384;
        int hh = j & 1, w = (j >> 1) & 3, lane = (j >> 3) & 31;
        int ktp = (j >> 8) & 3, nt = (j >> 10) & 7, c = (j >> 13) & 15;
        int kt = 2 * ktp + (w >> 1), pair = w & 1;
        int q = lane & 3, g = lane >> 2;
        int k = kt * 16 + pair * 8 + 2 * q + hh, col = c * 64 + nt * 8 + g;
        g_W2F[j] = __float2half_rn(W2[k * 1024 + col]);
    }
}

// ---------------- count: cnt[dst] += 1 (runs before k_fused) ----------------
__global__ void k_count(const int* __restrict__ dstp) {
    int i = blockIdx.x * blockDim.x + threadIdx.x;
    if (i < E_TOTAL) atomicAdd(&g_cnt[__ldg(dstp + i)], 1.0f);
}

// ---------------- fused kernel ----------------
__global__ void __launch_bounds__(256, 2)
k_fused(const float* __restrict__ xfeat, const float* __restrict__ esh,
        const float* __restrict__ emb, const float* __restrict__ b1,
        const float* __restrict__ b2, const int* __restrict__ src,
        const int* __restrict__ dstp, float* __restrict__ out) {
    extern __shared__ float sm[];
    __half* hs = (__half*)sm;                    // 128 x 136 halves (272B rows)
    char* wsc = (char*)(sm + WS_OFF);
    const uint32_t wsb = (uint32_t)__cvta_generic_to_shared(wsc);
    const int tid = threadIdx.x, wid = tid >> 5, lane = tid & 31;
    const int qq = lane & 3, gg = lane >> 2;
    const int eBase = blockIdx.x * EPB;
    const int r0 = 16 * wid + gg, r1 = r0 + 8;

    // ---- stage emb tile as fp16 ----
#pragma unroll
    for (int it = 0; it < 16; it++) {
        int qi = it * 256 + tid;
        int rr = qi >> 5, c4 = qi & 31;
        float4 v = *(const float4*)(emb + (size_t)(eBase + rr) * 128 + 4 * c4);
        __half2 p0 = __floats2half2_rn(v.x, v.y);
        __half2 p1 = __floats2half2_rn(v.z, v.w);
        uint2 pk = {*(unsigned*)&p0, *(unsigned*)&p1};
        *(uint2*)((char*)hs + rr * 272 + 8 * c4) = pk;
    }
    // ---- stage W1F (32KB) via cp.async ----
#pragma unroll
    for (int it = 0; it < 8; it++)
        cpasync16(wsb + (it * 256 + tid) * 16, (const char*)g_W1F + (it * 256 + tid) * 16);
    cpcommit();

    // ---- per-edge TP coefficients (2 threads / edge), mean folded via inv ----
    {
        int e = tid >> 1, ge = eBase + e, u0 = (tid & 1) * 8;
        int si = __ldg(src + ge);
        int dn = __ldg(dstp + ge);
        float inv = 1.0f / fmaxf(__ldg(&g_cnt[dn]), 1.0f);
        const float* x = xfeat + (size_t)si * 64;
        float4 shv = *(const float4*)(esh + (size_t)ge * 4);
        float s1x = shv.y, s1y = shv.z, s1z = shv.w;
        float4 aq = *(const float4*)(x + u0), bq = *(const float4*)(x + u0 + 4);
        float sv[8] = {aq.x, aq.y, aq.z, aq.w, bq.x, bq.y, bq.z, bq.w};
        float vv[24];
#pragma unroll
        for (int p = 0; p < 6; p++) {
            float4 t = *(const float4*)(x + 16 + 3 * u0 + 4 * p);
            vv[4*p] = t.x; vv[4*p+1] = t.y; vv[4*p+2] = t.z; vv[4*p+3] = t.w;
        }
#pragma unroll
        for (int du = 0; du < 8; du++) {
            int u = u0 + du;
            float v0 = vv[3*du], v1 = vv[3*du+1], v2 = vv[3*du+2];
            sm[SV_OFF + e * 17 + u] = inv * sv[du];
            sm[CS1_OFF + e * 17 + u] = inv * INV_SQRT3 * (v0 * s1x + v1 * s1y + v2 * s1z);
            sm[VV_OFF + e * 49 + 3 * u + 0] = inv * v0;
            sm[VV_OFF + e * 49 + 3 * u + 1] = inv * v1;
            sm[VV_OFF + e * 49 + 3 * u + 2] = inv * v2;
        }
        if ((tid & 1) == 0) {
            *(float4*)(sm + SH_OFF + e * 4) = shv;
            ((int*)(sm + DST_OFF))[e] = dn;
        }
    }
    cpwait0();
    __syncthreads();

    // ---- A fragments ----
    unsigned a[8][4];
#pragma unroll
    for (int kt = 0; kt < 8; kt++) {
        a[kt][0] = *(const unsigned*)((char*)hs + r0 * 272 + kt * 32 + 4 * qq);
        a[kt][1] = *(const unsigned*)((char*)hs + r1 * 272 + kt * 32 + 4 * qq);
        a[kt][2] = *(const unsigned*)((char*)hs + r0 * 272 + kt * 32 + 4 * qq + 16);
        a[kt][3] = *(const unsigned*)((char*)hs + r1 * 272 + kt * 32 + 4 * qq + 16);
    }

    // ---- GEMM1: paired-kt LDS.128 B, bias init, gelu -> h over emb ----
#pragma unroll
    for (int h = 0; h < 2; h++) {
        float acc[8][4];
#pragma unroll
        for (int nt = 0; nt < 8; nt++) {
            float2 bb = *(const float2*)(b1 + h * 64 + nt * 8 + 2 * qq);
            acc[nt][0] = bb.x; acc[nt][1] = bb.y;
            acc[nt][2] = bb.x; acc[nt][3] = bb.y;
        }
        const uint4* wb = (const uint4*)(wsc + h * 16384);
#pragma unroll
        for (int ktp = 0; ktp < 4; ktp++)
#pragma unroll
            for (int nt = 0; nt < 8; nt++) {
                uint4 b = wb[(nt * 4 + ktp) * 32 + lane];
                mma16(acc[nt], a[2*ktp],     b.x, b.y);
                mma16(acc[nt], a[2*ktp + 1], b.z, b.w);
            }
#pragma unroll
        for (int nt = 0; nt < 8; nt++) {
            int col = h * 64 + nt * 8 + 2 * qq;
            __half2 h0 = __floats2half2_rn(gelu_exact(acc[nt][0]), gelu_exact(acc[nt][1]));
            __half2 h1 = __floats2half2_rn(gelu_exact(acc[nt][2]), gelu_exact(acc[nt][3]));
            *(__half2*)((char*)hs + r0 * 272 + col * 2) = h0;
            *(__half2*)((char*)hs + r1 * 272 + col * 2) = h1;
        }
    }
    __syncwarp();
    // reload A fragments = h
#pragma unroll
    for (int kt = 0; kt < 8; kt++) {
        a[kt][0] = *(const unsigned*)((char*)hs + r0 * 272 + kt * 32 + 4 * qq);
        a[kt][1] = *(const unsigned*)((char*)hs + r1 * 272 + kt * 32 + 4 * qq);
        a[kt][2] = *(const unsigned*)((char*)hs + r0 * 272 + kt * 32 + 4 * qq + 16);
        a[kt][3] = *(const unsigned*)((char*)hs + r1 * 272 + kt * 32 + 4 * qq + 16);
    }
    __syncthreads();   // all warps done with W1F in ws

    const float sh0_0 = sm[SH_OFF + r0 * 4], sh0_1 = sm[SH_OFF + r1 * 4];

    // ---- stage W2 chunk 0 into buf 0 ----
#pragma unroll
    for (int it = 0; it < 4; it++)
        cpasync16(wsb + (it * 256 + tid) * 16, (const char*)g_W2F + (it * 256 + tid) * 16);
    cpcommit();
    cpwait0();
    __syncthreads();

    float r0a[2][4], r2a[2][4], r3a[2][4][3];
#pragma unroll
    for (int ei = 0; ei < 2; ei++)
#pragma unroll
        for (int s = 0; s < 4; s++) {
            r0a[ei][s] = 0.0f; r2a[ei][s] = 0.0f;
            r3a[ei][s][0] = 0.0f; r3a[ei][s][1] = 0.0f; r3a[ei][s][2] = 0.0f;
        }

#pragma unroll 1
    for (int c = 0; c < 16; c++) {
        if (c < 15) {   // prefetch next chunk into other buffer
#pragma unroll
            for (int it = 0; it < 4; it++)
                cpasync16(wsb + ((c + 1) & 1) * 16384 + (it * 256 + tid) * 16,
                          (const char*)g_W2F + (c + 1) * 16384 + (it * 256 + tid) * 16);
            cpcommit();
        }
        const uint4* wb = (const uint4*)(wsc + (c & 1) * 16384);
        const int t = c >> 2, g4 = c & 3;

#pragma unroll
        for (int half = 0; half < 2; half++) {
            float acc[4][4];
#pragma unroll
            for (int ntl = 0; ntl < 4; ntl++) {
                int nt = half * 4 + ntl;
                float2 bb = *(const float2*)(b2 + c * 64 + nt * 8 + 2 * qq);
                acc[ntl][0] = bb.x; acc[ntl][1] = bb.y;
                acc[ntl][2] = bb.x; acc[ntl][3] = bb.y;
            }
#pragma unroll
            for (int ktp = 0; ktp < 4; ktp++)
#pragma unroll
                for (int ntl = 0; ntl < 4; ntl++) {
                    uint4 b = wb[((half * 4 + ntl) * 4 + ktp) * 32 + lane];
                    mma16(acc[ntl], a[2*ktp],     b.x, b.y);
                    mma16(acc[ntl], a[2*ktp + 1], b.z, b.w);
                }

            if (t <= 2) {
                float cc0[2], cc1[2];
#pragma unroll
                for (int i = 0; i < 2; i++) {
                    int u = 4 * g4 + half * 2 + i;
                    if (t == 0) {
                        cc0[i] = sh0_0 * sm[SV_OFF + r0 * 17 + u];
                        cc1[i] = sh0_1 * sm[SV_OFF + r1 * 17 + u];
                    } else if (t == 1) {
                        cc0[i] = sm[CS1_OFF + r0 * 17 + u];
                        cc1[i] = sm[CS1_OFF + r1 * 17 + u];
                    } else {
                        cc0[i] = sm[SV_OFF + r0 * 17 + u];
                        cc1[i] = sm[SV_OFF + r1 * 17 + u];
                    }
                }
                float (*ra)[4] = (t == 2) ? r2a : r0a;
#pragma unroll
                for (int ntl = 0; ntl < 4; ntl++) {
                    int i = ntl >> 1, p = ntl & 1;
                    ra[0][2*p]   = fmaf(cc0[i], acc[ntl][0], ra[0][2*p]);
                    ra[0][2*p+1] = fmaf(cc0[i], acc[ntl][1], ra[0][2*p+1]);
                    ra[1][2*p]   = fmaf(cc1[i], acc[ntl][2], ra[1][2*p]);
                    ra[1][2*p+1] = fmaf(cc1[i], acc[ntl][3], ra[1][2*p+1]);
                }
            } else {
                float v0[2][3], v1[2][3];
#pragma unroll
                for (int i = 0; i < 2; i++)
#pragma unroll
                    for (int m = 0; m < 3; m++) {
                        int u = 4 * g4 + half * 2 + i;
                        v0[i][m] = sm[VV_OFF + r0 * 49 + 3 * u + m];
                        v1[i][m] = sm[VV_OFF + r1 * 49 + 3 * u + m];
                    }
#pragma unroll
                for (int ntl = 0; ntl < 4; ntl++) {
                    int i = ntl >> 1, p = ntl & 1;
                    float d0 = sh0_0 * acc[ntl][0], d1 = sh0_0 * acc[ntl][1];
                    float d2 = sh0_1 * acc[ntl][2], d3 = sh0_1 * acc[ntl][3];
#pragma unroll
                    for (int m = 0; m < 3; m++) {
                        r3a[0][2*p][m]   = fmaf(v0[i][m], d0, r3a[0][2*p][m]);
                        r3a[0][2*p+1][m] = fmaf(v0[i][m], d1, r3a[0][2*p+1][m]);
                        r3a[1][2*p][m]   = fmaf(v1[i][m], d2, r3a[1][2*p][m]);
                        r3a[1][2*p+1][m] = fmaf(v1[i][m], d3, r3a[1][2*p+1][m]);
                    }
                }
            }
        }

        if (c == 7) {   // scatter out0
            int dn0 = ((int*)(sm + DST_OFF))[r0];
            int dn1 = ((int*)(sm + DST_OFF))[r1];
            float* op0 = out + (size_t)dn0 * 64;
            float* op1 = out + (size_t)dn1 * 64;
            red2(op0 + 2*qq,     ALPHA * r0a[0][0], ALPHA * r0a[0][1]);
            red2(op0 + 2*qq + 8, ALPHA * r0a[0][2], ALPHA * r0a[0][3]);
            red2(op1 + 2*qq,     ALPHA * r0a[1][0], ALPHA * r0a[1][1]);
            red2(op1 + 2*qq + 8, ALPHA * r0a[1][2], ALPHA * r0a[1][3]);
        }
        if (c == 15) {  // scatter out1
            int dns[2] = {((int*)(sm + DST_OFF))[r0], ((int*)(sm + DST_OFF))[r1]};
            int ers[2] = {r0, r1};
#pragma unroll
            for (int ei = 0; ei < 2; ei++) {
                float s1m[3];
#pragma unroll
                for (int m = 0; m < 3; m++) s1m[m] = sm[SH_OFF + ers[ei] * 4 + 1 + m];
                float* op = out + (size_t)dns[ei] * 64 + 16;
                float va[4][3];
#pragma unroll
                for (int s = 0; s < 4; s++)
#pragma unroll
                    for (int m = 0; m < 3; m++)
                        va[s][m] = ALPHA * fmaf(s1m[m], r2a[ei][s], r3a[ei][s][m]);
                red2(op + 6*qq + 0, va[0][0], va[0][1]);
                red2(op + 6*qq + 2, va[0][2], va[1][0]);
                red2(op + 6*qq + 4, va[1][1], va[1][2]);
                red2(op + 6*qq + 24, va[2][0], va[2][1]);
                red2(op + 6*qq + 26, va[2][2], va[3][0]);
                red2(op + 6*qq + 28, va[3][1], va[3][2]);
            }
        }
        cpwait0();
        __syncthreads();
    }
}

// ---------------------------------------------------------------------------
extern "C" void kernel_launch(void* const* d_in, const int* in_sizes, int n_in,
                              void* d_out, int out_size) {
    const float* xfeat = (const float*)d_in[0];
    const float* eshv  = (const float*)d_in[1];
    const float* emb   = (const float*)d_in[2];
    const float* W1    = (const float*)d_in[3];
    const float* b1    = (const float*)d_in[4];
    const float* W2    = (const float*)d_in[5];
    const float* b2    = (const float*)d_in[6];
    const int*   src   = (const int*)d_in[7];
    const int*   dstp  = (const int*)d_in[8];
    float* out = (float*)d_out;

    cudaFuncSetAttribute(k_fused, cudaFuncAttributeMaxDynamicSharedMemorySize, SMEM_BYTES);

    k_prep<<<(NNODES * 16 + 255) / 256, 256>>>(W1, W2, (float4*)out);
    k_count<<<(E_TOTAL + 255) / 256, 256>>>(dstp);
    k_fused<<<E_TOTAL / EPB, 256, SMEM_BYTES>>>(xfeat, eshv, emb, b1, b2, src, dstp, out);
}

// round 15
// speedup vs baseline: 1.2408x; 1.0384x over previous
#include <cuda_runtime.h>
#include <cuda_fp16.h>
#include <math.h>
#include <cstdint>

#define E_TOTAL 160000
#define NNODES  10000
#define EPB     64
#define INV_SQRT3 0.5773502691896258f
#define ALPHA     0.17677669529663687f

// ---- smem float offsets ----
// HS: 64 rows x 136 halves (emb->h tile, fp16) = [0, 4352)
#define WS_OFF   4352     // 2 x 16KB W fragment buffers (fp16), 8192 f
#define CS1_OFF  12544    // [64][17] f32: INV_SQRT3*(v . sh1)
#define SV_OFF   13632    // [64][17] f32: raw s
#define VV_OFF   14720    // [64][49] f32: raw v (3u+m)
#define SH_OFF   17856    // [64][4]  f32: edge_sh
#define DST_OFF  18112    // [64] int
#define TOTF     18176
#define SMEM_BYTES (TOTF * 4)   // 72704 B -> 3 CTAs/SM

// paired-kt fragment layout (uint4 per lane serves kt=2*ktp and 2*ktp+1):
// half idx = ((((blk*8+nt)*4+ktp)*32+lane)*4 + w)*2 + hh,  kt=2*ktp+(w>>1), pair=w&1
__device__ __align__(16) __half g_W1F[16384];        // 32KB
__device__ __align__(16) __half g_W2F[16 * 8192];    // 16 chunks x 16KB
__device__ float g_cnt[NNODES];

__device__ __forceinline__ float gelu_exact(float x) {
    return 0.5f * x * (1.0f + erff(x * 0.7071067811865476f));
}
__device__ __forceinline__ void red2(float* p, float a, float b) {
    asm volatile("red.global.add.v2.f32 [%0], {%1, %2};"
                 :: "l"(p), "f"(a), "f"(b) : "memory");
}
__device__ __forceinline__ void mma16(float* c, const unsigned* a,
                                      unsigned b0, unsigned b1) {
    asm("mma.sync.aligned.m16n8k16.row.col.f32.f16.f16.f32 "
        "{%0,%1,%2,%3}, {%4,%5,%6,%7}, {%8,%9}, {%0,%1,%2,%3};"
        : "+f"(c[0]), "+f"(c[1]), "+f"(c[2]), "+f"(c[3])
        : "r"(a[0]), "r"(a[1]), "r"(a[2]), "r"(a[3]), "r"(b0), "r"(b1));
}
__device__ __forceinline__ void cpasync16(uint32_t s, const void* g) {
    asm volatile("cp.async.cg.shared.global [%0], [%1], 16;" :: "r"(s), "l"(g));
}
__device__ __forceinline__ void cpcommit() {
    asm volatile("cp.async.commit_group;" ::: "memory");
}
__device__ __forceinline__ void cpwait0() {
    asm volatile("cp.async.wait_group 0;" ::: "memory");
}

// ---------------- prep: zero out+cnt, fp16 weights in paired-kt order ----------
__global__ void k_prep(const float* __restrict__ W1, const float* __restrict__ W2,
                       float4* __restrict__ out4) {
    int i = blockIdx.x * 256 + threadIdx.x;
    if (i < NNODES * 16) out4[i] = make_float4(0.f, 0.f, 0.f, 0.f);
    if (i < NNODES) g_cnt[i] = 0.0f;
    if (i < 16384) {
        int hh = i & 1, w = (i >> 1) & 3, lane = (i >> 3) & 31;
        int ktp = (i >> 8) & 3, nt = (i >> 10) & 7, h = (i >> 13) & 1;
        int kt = 2 * ktp + (w >> 1), pair = w & 1;
        int q = lane & 3, g = lane >> 2;
        int k = kt * 16 + pair * 8 + 2 * q + hh, n = h * 64 + nt * 8 + g;
        g_W1F[i] = __float2half_rn(W1[k * 128 + n]);
    } else if (i < 16384 + 131072) {
        int j = i - 16384;
        int hh = j & 1, w = (j >> 1) & 3, lane = (j >> 3) & 31;
        int ktp = (j >> 8) & 3, nt = (j >> 10) & 7, c = (j >> 13) & 15;
        int kt = 2 * ktp + (w >> 1), pair = w & 1;
        int q = lane & 3, g = lane >> 2;
        int k = kt * 16 + pair * 8 + 2 * q + hh, col = c * 64 + nt * 8 + g;
        g_W2F[j] = __float2half_rn(W2[k * 1024 + col]);
    }
}

__global__ void k_norm(float4* __restrict__ out4) {
    int i = blockIdx.x * blockDim.x + threadIdx.x;
    if (i < NNODES * 16) {
        float inv = 1.0f / fmaxf(g_cnt[i >> 4], 1.0f);
        float4 o = out4[i];
        o.x *= inv; o.y *= inv; o.z *= inv; o.w *= inv;
        out4[i] = o;
    }
}

// ---------------- fused kernel: 4 warps x 16 rows, 64 edges/block --------------
__global__ void __launch_bounds__(128, 3)
k_fused(const float* __restrict__ xfeat, const float* __restrict__ esh,
        const float* __restrict__ emb, const float* __restrict__ b1,
        const float* __restrict__ b2, const int* __restrict__ src,
        const int* __restrict__ dstp, float* __restrict__ out) {
    extern __shared__ float sm[];
    __half* hs = (__half*)sm;                    // 64 x 136 halves (272B rows)
    char* wsc = (char*)(sm + WS_OFF);
    const uint32_t wsb = (uint32_t)__cvta_generic_to_shared(wsc);
    const int tid = threadIdx.x, wid = tid >> 5, lane = tid & 31;
    const int qq = lane & 3, gg = lane >> 2;
    const int eBase = blockIdx.x * EPB;
    const int r0 = 16 * wid + gg, r1 = r0 + 8;

    // ---- stage emb tile as fp16 (64 rows) ----
#pragma unroll
    for (int it = 0; it < 16; it++) {
        int qi = it * 128 + tid;
        int rr = qi >> 5, c4 = qi & 31;
        float4 v = *(const float4*)(emb + (size_t)(eBase + rr) * 128 + 4 * c4);
        __half2 p0 = __floats2half2_rn(v.x, v.y);
        __half2 p1 = __floats2half2_rn(v.z, v.w);
        uint2 pk = {*(unsigned*)&p0, *(unsigned*)&p1};
        *(uint2*)((char*)hs + rr * 272 + 8 * c4) = pk;
    }
    // ---- stage W1F (32KB) via cp.async ----
#pragma unroll
    for (int it = 0; it < 16; it++)
        cpasync16(wsb + (it * 128 + tid) * 16, (const char*)g_W1F + (it * 128 + tid) * 16);
    cpcommit();

    // ---- per-edge TP coefficients (2 threads / edge, warp-local rows) ----
    {
        int e = tid >> 1, ge = eBase + e, u0 = (tid & 1) * 8;
        int si = __ldg(src + ge);
        const float* x = xfeat + (size_t)si * 64;
        float4 shv = *(const float4*)(esh + (size_t)ge * 4);
        float s1x = shv.y, s1y = shv.z, s1z = shv.w;
        float4 aq = *(const float4*)(x + u0), bq = *(const float4*)(x + u0 + 4);
        float sv[8] = {aq.x, aq.y, aq.z, aq.w, bq.x, bq.y, bq.z, bq.w};
        float vv[24];
#pragma unroll
        for (int p = 0; p < 6; p++) {
            float4 t = *(const float4*)(x + 16 + 3 * u0 + 4 * p);
            vv[4*p] = t.x; vv[4*p+1] = t.y; vv[4*p+2] = t.z; vv[4*p+3] = t.w;
        }
#pragma unroll
        for (int du = 0; du < 8; du++) {
            int u = u0 + du;
            float v0 = vv[3*du], v1 = vv[3*du+1], v2 = vv[3*du+2];
            sm[SV_OFF + e * 17 + u] = sv[du];
            sm[CS1_OFF + e * 17 + u] = INV_SQRT3 * (v0 * s1x + v1 * s1y + v2 * s1z);
            sm[VV_OFF + e * 49 + 3 * u + 0] = v0;
            sm[VV_OFF + e * 49 + 3 * u + 1] = v1;
            sm[VV_OFF + e * 49 + 3 * u + 2] = v2;
        }
        if ((tid & 1) == 0) {
            *(float4*)(sm + SH_OFF + e * 4) = shv;
            ((int*)(sm + DST_OFF))[e] = __ldg(dstp + ge);
        }
    }
    cpwait0();
    __syncthreads();

    // ---- A fragments ----
    unsigned a[8][4];
#pragma unroll
    for (int kt = 0; kt < 8; kt++) {
        a[kt][0] = *(const unsigned*)((char*)hs + r0 * 272 + kt * 32 + 4 * qq);
        a[kt][1] = *(const unsigned*)((char*)hs + r1 * 272 + kt * 32 + 4 * qq);
        a[kt][2] = *(const unsigned*)((char*)hs + r0 * 272 + kt * 32 + 4 * qq + 16);
        a[kt][3] = *(const unsigned*)((char*)hs + r1 * 272 + kt * 32 + 4 * qq + 16);
    }

    // ---- GEMM1: paired-kt LDS.128 B, bias init, gelu -> h over emb ----
#pragma unroll
    for (int h = 0; h < 2; h++) {
        float acc[8][4];
#pragma unroll
        for (int nt = 0; nt < 8; nt++) {
            float2 bb = *(const float2*)(b1 + h * 64 + nt * 8 + 2 * qq);
            acc[nt][0] = bb.x; acc[nt][1] = bb.y;
            acc[nt][2] = bb.x; acc[nt][3] = bb.y;
        }
        const uint4* wb = (const uint4*)(wsc + h * 16384);
#pragma unroll
        for (int ktp = 0; ktp < 4; ktp++)
#pragma unroll
            for (int nt = 0; nt < 8; nt++) {
                uint4 b = wb[(nt * 4 + ktp) * 32 + lane];
                mma16(acc[nt], a[2*ktp],     b.x, b.y);
                mma16(acc[nt], a[2*ktp + 1], b.z, b.w);
            }
#pragma unroll
        for (int nt = 0; nt < 8; nt++) {
            int col = h * 64 + nt * 8 + 2 * qq;
            __half2 h0 = __floats2half2_rn(gelu_exact(acc[nt][0]), gelu_exact(acc[nt][1]));
            __half2 h1 = __floats2half2_rn(gelu_exact(acc[nt][2]), gelu_exact(acc[nt][3]));
            *(__half2*)((char*)hs + r0 * 272 + col * 2) = h0;
            *(__half2*)((char*)hs + r1 * 272 + col * 2) = h1;
        }
    }
    __syncwarp();
    // reload A fragments = h
#pragma unroll
    for (int kt = 0; kt < 8; kt++) {
        a[kt][0] = *(const unsigned*)((char*)hs + r0 * 272 + kt * 32 + 4 * qq);
        a[kt][1] = *(const unsigned*)((char*)hs + r1 * 272 + kt * 32 + 4 * qq);
        a[kt][2] = *(const unsigned*)((char*)hs + r0 * 272 + kt * 32 + 4 * qq + 16);
        a[kt][3] = *(const unsigned*)((char*)hs + r1 * 272 + kt * 32 + 4 * qq + 16);
    }
    __syncthreads();   // all warps done with W1F in ws

    const float sh0_0 = sm[SH_OFF + r0 * 4], sh0_1 = sm[SH_OFF + r1 * 4];

    // ---- stage W2 chunk 0 into buf 0 ----
#pragma unroll
    for (int it = 0; it < 8; it++)
        cpasync16(wsb + (it * 128 + tid) * 16, (const char*)g_W2F + (it * 128 + tid) * 16);
    cpcommit();
    cpwait0();
    __syncthreads();

    float r0a[2][4], r2a[2][4], r3a[2][4][3];
#pragma unroll
    for (int ei = 0; ei < 2; ei++)
#pragma unroll
        for (int s = 0; s < 4; s++) {
            r0a[ei][s] = 0.0f; r2a[ei][s] = 0.0f;
            r3a[ei][s][0] = 0.0f; r3a[ei][s][1] = 0.0f; r3a[ei][s][2] = 0.0f;
        }

#pragma unroll 1
    for (int c = 0; c < 16; c++) {
        if (c < 15) {   // prefetch next chunk into other buffer
#pragma unroll
            for (int it = 0; it < 8; it++)
                cpasync16(wsb + ((c + 1) & 1) * 16384 + (it * 128 + tid) * 16,
                          (const char*)g_W2F + (c + 1) * 16384 + (it * 128 + tid) * 16);
            cpcommit();
        }
        const uint4* wb = (const uint4*)(wsc + (c & 1) * 16384);
        const int t = c >> 2, g4 = c & 3;

#pragma unroll
        for (int half = 0; half < 2; half++) {
            float acc[4][4];
#pragma unroll
            for (int ntl = 0; ntl < 4; ntl++) {
                int nt = half * 4 + ntl;
                float2 bb = *(const float2*)(b2 + c * 64 + nt * 8 + 2 * qq);
                acc[ntl][0] = bb.x; acc[ntl][1] = bb.y;
                acc[ntl][2] = bb.x; acc[ntl][3] = bb.y;
            }
#pragma unroll
            for (int ktp = 0; ktp < 4; ktp++)
#pragma unroll
                for (int ntl = 0; ntl < 4; ntl++) {
                    uint4 b = wb[((half * 4 + ntl) * 4 + ktp) * 32 + lane];
                    mma16(acc[ntl], a[2*ktp],     b.x, b.y);
                    mma16(acc[ntl], a[2*ktp + 1], b.z, b.w);
                }

            if (t <= 2) {
                float cc0[2], cc1[2];
#pragma unroll
                for (int i = 0; i < 2; i++) {
                    int u = 4 * g4 + half * 2 + i;
                    if (t == 0) {
                        cc0[i] = sh0_0 * sm[SV_OFF + r0 * 17 + u];
                        cc1[i] = sh0_1 * sm[SV_OFF + r1 * 17 + u];
                    } else if (t == 1) {
                        cc0[i] = sm[CS1_OFF + r0 * 17 + u];
                        cc1[i] = sm[CS1_OFF + r1 * 17 + u];
                    } else {
                        cc0[i] = sm[SV_OFF + r0 * 17 + u];
                        cc1[i] = sm[SV_OFF + r1 * 17 + u];
                    }
                }
                float (*ra)[4] = (t == 2) ? r2a : r0a;
#pragma unroll
                for (int ntl = 0; ntl < 4; ntl++) {
                    int i = ntl >> 1, p = ntl & 1;
                    ra[0][2*p]   = fmaf(cc0[i], acc[ntl][0], ra[0][2*p]);
                    ra[0][2*p+1] = fmaf(cc0[i], acc[ntl][1], ra[0][2*p+1]);
                    ra[1][2*p]   = fmaf(cc1[i], acc[ntl][2], ra[1][2*p]);
                    ra[1][2*p+1] = fmaf(cc1[i], acc[ntl][3], ra[1][2*p+1]);
                }
            } else {
                float v0[2][3], v1[2][3];
#pragma unroll
                for (int i = 0; i < 2; i++)
#pragma unroll
                    for (int m = 0; m < 3; m++) {
                        int u = 4 * g4 + half * 2 + i;
                        v0[i][m] = sm[VV_OFF + r0 * 49 + 3 * u + m];
                        v1[i][m] = sm[VV_OFF + r1 * 49 + 3 * u + m];
                    }
#pragma unroll
                for (int ntl = 0; ntl < 4; ntl++) {
                    int i = ntl >> 1, p = ntl & 1;
                    float d0 = sh0_0 * acc[ntl][0], d1 = sh0_0 * acc[ntl][1];
                    float d2 = sh0_1 * acc[ntl][2], d3 = sh0_1 * acc[ntl][3];
#pragma unroll
                    for (int m = 0; m < 3; m++) {
                        r3a[0][2*p][m]   = fmaf(v0[i][m], d0, r3a[0][2*p][m]);
                        r3a[0][2*p+1][m] = fmaf(v0[i][m], d1, r3a[0][2*p+1][m]);
                        r3a[1][2*p][m]   = fmaf(v1[i][m], d2, r3a[1][2*p][m]);
                        r3a[1][2*p+1][m] = fmaf(v1[i][m], d3, r3a[1][2*p+1][m]);
                    }
                }
            }
        }

        if (c == 7) {   // scatter out0
            int dn0 = ((int*)(sm + DST_OFF))[r0];
            int dn1 = ((int*)(sm + DST_OFF))[r1];
            float* op0 = out + (size_t)dn0 * 64;
            float* op1 = out + (size_t)dn1 * 64;
            red2(op0 + 2*qq,     ALPHA * r0a[0][0], ALPHA * r0a[0][1]);
            red2(op0 + 2*qq + 8, ALPHA * r0a[0][2], ALPHA * r0a[0][3]);
            red2(op1 + 2*qq,     ALPHA * r0a[1][0], ALPHA * r0a[1][1]);
            red2(op1 + 2*qq + 8, ALPHA * r0a[1][2], ALPHA * r0a[1][3]);
            if (qq == 0) {
                atomicAdd(&g_cnt[dn0], 1.0f);
                atomicAdd(&g_cnt[dn1], 1.0f);
            }
        }
        if (c == 15) {  // scatter out1
            int dns[2] = {((int*)(sm + DST_OFF))[r0], ((int*)(sm + DST_OFF))[r1]};
            int ers[2] = {r0, r1};
#pragma unroll
            for (int ei = 0; ei < 2; ei++) {
                float s1m[3];
#pragma unroll
                for (int m = 0; m < 3; m++) s1m[m] = sm[SH_OFF + ers[ei] * 4 + 1 + m];
                float* op = out + (size_t)dns[ei] * 64 + 16;
                float va[4][3];
#pragma unroll
                for (int s = 0; s < 4; s++)
#pragma unroll
                    for (int m = 0; m < 3; m++)
                        va[s][m] = ALPHA * fmaf(s1m[m], r2a[ei][s], r3a[ei][s][m]);
                red2(op + 6*qq + 0, va[0][0], va[0][1]);
                red2(op + 6*qq + 2, va[0][2], va[1][0]);
                red2(op + 6*qq + 4, va[1][1], va[1][2]);
                red2(op + 6*qq + 24, va[2][0], va[2][1]);
                red2(op + 6*qq + 26, va[2][2], va[3][0]);
                red2(op + 6*qq + 28, va[3][1], va[3][2]);
            }
        }
        cpwait0();
        __syncthreads();
    }
}

// ---------------------------------------------------------------------------
extern "C" void kernel_launch(void* const* d_in, const int* in_sizes, int n_in,
                              void* d_out, int out_size) {
    const float* xfeat = (const float*)d_in[0];
    const float* eshv  = (const float*)d_in[1];
    const float* emb   = (const float*)d_in[2];
    const float* W1    = (const float*)d_in[3];
    const float* b1    = (const float*)d_in[4];
    const float* W2    = (const float*)d_in[5];
    const float* b2    = (const float*)d_in[6];
    const int*   src   = (const int*)d_in[7];
    const int*   dstp  = (const int*)d_in[8];
    float* out = (float*)d_out;

    cudaFuncSetAttribute(k_fused, cudaFuncAttributeMaxDynamicSharedMemorySize, SMEM_BYTES);

    k_prep<<<(NNODES * 16 + 255) / 256, 256>>>(W1, W2, (float4*)out);
    k_fused<<<E_TOTAL / EPB, 128, SMEM_BYTES>>>(xfeat, eshv, emb, b1, b2, src, dstp, out);
    k_norm<<<(NNODES * 16 + 255) / 256, 256>>>((float4*)out);
}

// round 17
// speedup vs baseline: 1.2492x; 1.0067x over previous
#include <cuda_runtime.h>
#include <cuda_fp16.h>
#include <math.h>
#include <cstdint>

#define E_TOTAL 160000
#define NNODES  10000
#define EPB     64
#define INV_SQRT3 0.5773502691896258f
#define ALPHA     0.17677669529663687f

// ---- smem float offsets ----
// HS: 64 rows x 136 halves (emb->h tile, fp16) = [0, 4352)
#define WS_OFF   4352     // 2 x 16KB W fragment buffers (fp16), 8192 f
#define CS1_OFF  12544    // [64][17] f32: INV_SQRT3*(v . sh1)
#define SV_OFF   13632    // [64][17] f32: raw s
#define VV_OFF   14720    // [64][49] f32: raw v (3u+m)
#define SH_OFF   17856    // [64][4]  f32: edge_sh
#define DST_OFF  18112    // [64] int
#define TOTF     18176
#define SMEM_BYTES (TOTF * 4)   // 72704 B -> 3 CTAs/SM

// paired-kt fragment layout (uint4 per lane serves kt=2*ktp and 2*ktp+1):
// half idx = ((((blk*8+nt)*4+ktp)*32+lane)*4 + w)*2 + hh,  kt=2*ktp+(w>>1), pair=w&1
__device__ __align__(16) __half g_W1F[16384];        // 32KB
__device__ __align__(16) __half g_W2F[16 * 8192];    // 16 chunks x 16KB
__device__ float g_cnt[NNODES];

__device__ __forceinline__ float gelu_exact(float x) {
    return 0.5f * x * (1.0f + erff(x * 0.7071067811865476f));
}
__device__ __forceinline__ void red2(float* p, float a, float b) {
    asm volatile("red.global.add.v2.f32 [%0], {%1, %2};"
                 :: "l"(p), "f"(a), "f"(b) : "memory");
}
__device__ __forceinline__ void mma16(float* c, const unsigned* a,
                                      unsigned b0, unsigned b1) {
    asm("mma.sync.aligned.m16n8k16.row.col.f32.f16.f16.f32 "
        "{%0,%1,%2,%3}, {%4,%5,%6,%7}, {%8,%9}, {%0,%1,%2,%3};"
        : "+f"(c[0]), "+f"(c[1]), "+f"(c[2]), "+f"(c[3])
        : "r"(a[0]), "r"(a[1]), "r"(a[2]), "r"(a[3]), "r"(b0), "r"(b1));
}
__device__ __forceinline__ void cpasync16(uint32_t s, const void* g) {
    asm volatile("cp.async.cg.shared.global [%0], [%1], 16;" :: "r"(s), "l"(g));
}
__device__ __forceinline__ void cpcommit() {
    asm volatile("cp.async.commit_group;" ::: "memory");
}
__device__ __forceinline__ void cpwait0() {
    asm volatile("cp.async.wait_group 0;" ::: "memory");
}

// ---------------- prep: zero out+cnt, fp16 weights in paired-kt order ----------
__global__ void k_prep(const float* __restrict__ W1, const float* __restrict__ W2,
                       float4* __restrict__ out4) {
    int i = blockIdx.x * 256 + threadIdx.x;
    if (i < NNODES * 16) out4[i] = make_float4(0.f, 0.f, 0.f, 0.f);
    if (i < NNODES) g_cnt[i] = 0.0f;
    if (i < 16384) {
        int hh = i & 1, w = (i >> 1) & 3, lane = (i >> 3) & 31;
        int ktp = (i >> 8) & 3, nt = (i >> 10) & 7, h = (i >> 13) & 1;
        int kt = 2 * ktp + (w >> 1), pair = w & 1;
        int q = lane & 3, g = lane >> 2;
        int k = kt * 16 + pair * 8 + 2 * q + hh, n = h * 64 + nt * 8 + g;
        g_W1F[i] = __float2half_rn(W1[k * 128 + n]);
    } else if (i < 16384 + 131072) {
        int j = i - 16384;
        int hh = j & 1, w = (j >> 1) & 3, lane = (j >> 3) & 31;
        int ktp = (j >> 8) & 3, nt = (j >> 10) & 7, c = (j >> 13) & 15;
        int kt = 2 * ktp + (w >> 1), pair = w & 1;
        int q = lane & 3, g = lane >> 2;
        int k = kt * 16 + pair * 8 + 2 * q + hh, col = c * 64 + nt * 8 + g;
        g_W2F[j] = __float2half_rn(W2[k * 1024 + col]);
    }
}

__global__ void k_norm(float4* __restrict__ out4) {
    int i = blockIdx.x * blockDim.x + threadIdx.x;
    if (i < NNODES * 16) {
        float inv = 1.0f / fmaxf(g_cnt[i >> 4], 1.0f);
        float4 o = out4[i];
        o.x *= inv; o.y *= inv; o.z *= inv; o.w *= inv;
        out4[i] = o;
    }
}

// ---------------- fused kernel: 4 warps x 16 rows, 64 edges/block --------------
__global__ void __launch_bounds__(128, 3)
k_fused(const float* __restrict__ xfeat, const float* __restrict__ esh,
        const float* __restrict__ emb, const float* __restrict__ b1,
        const float* __restrict__ b2, const int* __restrict__ src,
        const int* __restrict__ dstp, float* __restrict__ out) {
    extern __shared__ float sm[];
    __half* hs = (__half*)sm;                    // 64 x 136 halves (272B rows)
    char* wsc = (char*)(sm + WS_OFF);
    const uint32_t wsb = (uint32_t)__cvta_generic_to_shared(wsc);
    const int tid = threadIdx.x, wid = tid >> 5, lane = tid & 31;
    const int qq = lane & 3, gg = lane >> 2;
    const int eBase = blockIdx.x * EPB;
    const int r0 = 16 * wid + gg, r1 = r0 + 8;

    // ---- stage emb tile as fp16 (64 rows) ----
#pragma unroll
    for (int it = 0; it < 16; it++) {
        int qi = it * 128 + tid;
        int rr = qi >> 5, c4 = qi & 31;
        float4 v = *(const float4*)(emb + (size_t)(eBase + rr) * 128 + 4 * c4);
        __half2 p0 = __floats2half2_rn(v.x, v.y);
        __half2 p1 = __floats2half2_rn(v.z, v.w);
        uint2 pk = {*(unsigned*)&p0, *(unsigned*)&p1};
        *(uint2*)((char*)hs + rr * 272 + 8 * c4) = pk;
    }
    // ---- stage W1F (32KB) via cp.async ----
#pragma unroll
    for (int it = 0; it < 16; it++)
        cpasync16(wsb + (it * 128 + tid) * 16, (const char*)g_W1F + (it * 128 + tid) * 16);
    cpcommit();

    // ---- per-edge TP coefficients (2 threads / edge, warp-local rows) ----
    {
        int e = tid >> 1, ge = eBase + e, u0 = (tid & 1) * 8;
        int si = __ldg(src + ge);
        const float* x = xfeat + (size_t)si * 64;
        float4 shv = *(const float4*)(esh + (size_t)ge * 4);
        float s1x = shv.y, s1y = shv.z, s1z = shv.w;
        float4 aq = *(const float4*)(x + u0), bq = *(const float4*)(x + u0 + 4);
        float sv[8] = {aq.x, aq.y, aq.z, aq.w, bq.x, bq.y, bq.z, bq.w};
        float vv[24];
#pragma unroll
        for (int p = 0; p < 6; p++) {
            float4 t = *(const float4*)(x + 16 + 3 * u0 + 4 * p);
            vv[4*p] = t.x; vv[4*p+1] = t.y; vv[4*p+2] = t.z; vv[4*p+3] = t.w;
        }
#pragma unroll
        for (int du = 0; du < 8; du++) {
            int u = u0 + du;
            float v0 = vv[3*du], v1 = vv[3*du+1], v2 = vv[3*du+2];
            sm[SV_OFF + e * 17 + u] = sv[du];
            sm[CS1_OFF + e * 17 + u] = INV_SQRT3 * (v0 * s1x + v1 * s1y + v2 * s1z);
            sm[VV_OFF + e * 49 + 3 * u + 0] = v0;
            sm[VV_OFF + e * 49 + 3 * u + 1] = v1;
            sm[VV_OFF + e * 49 + 3 * u + 2] = v2;
        }
        if ((tid & 1) == 0) {
            *(float4*)(sm + SH_OFF + e * 4) = shv;
            ((int*)(sm + DST_OFF))[e] = __ldg(dstp + ge);
        }
    }
    cpwait0();
    __syncthreads();

    // ---- A fragments ----
    unsigned a[8][4];
#pragma unroll
    for (int kt = 0; kt < 8; kt++) {
        a[kt][0] = *(const unsigned*)((char*)hs + r0 * 272 + kt * 32 + 4 * qq);
        a[kt][1] = *(const unsigned*)((char*)hs + r1 * 272 + kt * 32 + 4 * qq);
        a[kt][2] = *(const unsigned*)((char*)hs + r0 * 272 + kt * 32 + 4 * qq + 16);
        a[kt][3] = *(const unsigned*)((char*)hs + r1 * 272 + kt * 32 + 4 * qq + 16);
    }

    // ---- GEMM1 split into halves; W2 chunk-0 prefetch hides under h=1 ----
#pragma unroll
    for (int h = 0; h < 2; h++) {
        float acc[8][4];
#pragma unroll
        for (int nt = 0; nt < 8; nt++) {
            float2 bb = *(const float2*)(b1 + h * 64 + nt * 8 + 2 * qq);
            acc[nt][0] = bb.x; acc[nt][1] = bb.y;
            acc[nt][2] = bb.x; acc[nt][3] = bb.y;
        }
        const uint4* wb = (const uint4*)(wsc + h * 16384);
#pragma unroll
        for (int ktp = 0; ktp < 4; ktp++)
#pragma unroll
            for (int nt = 0; nt < 8; nt++) {
                uint4 b = wb[(nt * 4 + ktp) * 32 + lane];
                mma16(acc[nt], a[2*ktp],     b.x, b.y);
                mma16(acc[nt], a[2*ktp + 1], b.z, b.w);
            }
#pragma unroll
        for (int nt = 0; nt < 8; nt++) {
            int col = h * 64 + nt * 8 + 2 * qq;
            __half2 h0 = __floats2half2_rn(gelu_exact(acc[nt][0]), gelu_exact(acc[nt][1]));
            __half2 h1 = __floats2half2_rn(gelu_exact(acc[nt][2]), gelu_exact(acc[nt][3]));
            *(__half2*)((char*)hs + r0 * 272 + col * 2) = h0;
            *(__half2*)((char*)hs + r1 * 272 + col * 2) = h1;
        }
        if (h == 0) {
            __syncthreads();   // all warps done reading WS buf0
            // prefetch W2 chunk 0 into buf0 while h=1 computes from buf1
#pragma unroll
            for (int it = 0; it < 8; it++)
                cpasync16(wsb + (it * 128 + tid) * 16,
                          (const char*)g_W2F + (it * 128 + tid) * 16);
            cpcommit();
        }
    }
    __syncwarp();
    // reload A fragments = h (HS only, overlaps chunk-0 landing)
#pragma unroll
    for (int kt = 0; kt < 8; kt++) {
        a[kt][0] = *(const unsigned*)((char*)hs + r0 * 272 + kt * 32 + 4 * qq);
        a[kt][1] = *(const unsigned*)((char*)hs + r1 * 272 + kt * 32 + 4 * qq);
        a[kt][2] = *(const unsigned*)((char*)hs + r0 * 272 + kt * 32 + 4 * qq + 16);
        a[kt][3] = *(const unsigned*)((char*)hs + r1 * 272 + kt * 32 + 4 * qq + 16);
    }
    const float sh0_0 = sm[SH_OFF + r0 * 4], sh0_1 = sm[SH_OFF + r1 * 4];

    cpwait0();
    __syncthreads();   // chunk0 ready; buf1 (W1F half1) free for chunk-1 prefetch

    float r0a[2][4], r2a[2][4], r3a[2][4][3];
#pragma unroll
    for (int ei = 0; ei < 2; ei++)
#pragma unroll
        for (int s = 0; s < 4; s++) {
            r0a[ei][s] = 0.0f; r2a[ei][s] = 0.0f;
            r3a[ei][s][0] = 0.0f; r3a[ei][s][1] = 0.0f; r3a[ei][s][2] = 0.0f;
        }

#pragma unroll 1
    for (int c = 0; c < 16; c++) {
        if (c < 15) {   // prefetch next chunk into other buffer
#pragma unroll
            for (int it = 0; it < 8; it++)
                cpasync16(wsb + ((c + 1) & 1) * 16384 + (it * 128 + tid) * 16,
                          (const char*)g_W2F + (c + 1) * 16384 + (it * 128 + tid) * 16);
            cpcommit();
        }
        const uint4* wb = (const uint4*)(wsc + (c & 1) * 16384);
        const int t = c >> 2, g4 = c & 3;

#pragma unroll
        for (int half = 0; half < 2; half++) {
            float acc[4][4];
#pragma unroll
            for (int ntl = 0; ntl < 4; ntl++) {
                int nt = half * 4 + ntl;
                float2 bb = *(const float2*)(b2 + c * 64 + nt * 8 + 2 * qq);
                acc[ntl][0] = bb.x; acc[ntl][1] = bb.y;
                acc[ntl][2] = bb.x; acc[ntl][3] = bb.y;
            }
#pragma unroll
            for (int ktp = 0; ktp < 4; ktp++)
#pragma unroll
                for (int ntl = 0; ntl < 4; ntl++) {
                    uint4 b = wb[((half * 4 + ntl) * 4 + ktp) * 32 + lane];
                    mma16(acc[ntl], a[2*ktp],     b.x, b.y);
                    mma16(acc[ntl], a[2*ktp + 1], b.z, b.w);
                }

            if (t <= 2) {
                float cc0[2], cc1[2];
#pragma unroll
                for (int i = 0; i < 2; i++) {
                    int u = 4 * g4 + half * 2 + i;
                    if (t == 0) {
                        cc0[i] = sh0_0 * sm[SV_OFF + r0 * 17 + u];
                        cc1[i] = sh0_1 * sm[SV_OFF + r1 * 17 + u];
                    } else if (t == 1) {
                        cc0[i] = sm[CS1_OFF + r0 * 17 + u];
                        cc1[i] = sm[CS1_OFF + r1 * 17 + u];
                    } else {
                        cc0[i] = sm[SV_OFF + r0 * 17 + u];
                        cc1[i] = sm[SV_OFF + r1 * 17 + u];
                    }
                }
                float (*ra)[4] = (t == 2) ? r2a : r0a;
#pragma unroll
                for (int ntl = 0; ntl < 4; ntl++) {
                    int i = ntl >> 1, p = ntl & 1;
                    ra[0][2*p]   = fmaf(cc0[i], acc[ntl][0], ra[0][2*p]);
                    ra[0][2*p+1] = fmaf(cc0[i], acc[ntl][1], ra[0][2*p+1]);
                    ra[1][2*p]   = fmaf(cc1[i], acc[ntl][2], ra[1][2*p]);
                    ra[1][2*p+1] = fmaf(cc1[i], acc[ntl][3], ra[1][2*p+1]);
                }
            } else {
                float v0[2][3], v1[2][3];
#pragma unroll
                for (int i = 0; i < 2; i++)
#pragma unroll
                    for (int m = 0; m < 3; m++) {
                        int u = 4 * g4 + half * 2 + i;
                        v0[i][m] = sm[VV_OFF + r0 * 49 + 3 * u + m];
                        v1[i][m] = sm[VV_OFF + r1 * 49 + 3 * u + m];
                    }
#pragma unroll
                for (int ntl = 0; ntl < 4; ntl++) {
                    int i = ntl >> 1, p = ntl & 1;
                    float d0 = sh0_0 * acc[ntl][0], d1 = sh0_0 * acc[ntl][1];
                    float d2 = sh0_1 * acc[ntl][2], d3 = sh0_1 * acc[ntl][3];
#pragma unroll
                    for (int m = 0; m < 3; m++) {
                        r3a[0][2*p][m]   = fmaf(v0[i][m], d0, r3a[0][2*p][m]);
                        r3a[0][2*p+1][m] = fmaf(v0[i][m], d1, r3a[0][2*p+1][m]);
                        r3a[1][2*p][m]   = fmaf(v1[i][m], d2, r3a[1][2*p][m]);
                        r3a[1][2*p+1][m] = fmaf(v1[i][m], d3, r3a[1][2*p+1][m]);
                    }
                }
            }
        }

        if (c == 7) {   // scatter out0
            int dn0 = ((int*)(sm + DST_OFF))[r0];
            int dn1 = ((int*)(sm + DST_OFF))[r1];
            float* op0 = out + (size_t)dn0 * 64;
            float* op1 = out + (size_t)dn1 * 64;
            red2(op0 + 2*qq,     ALPHA * r0a[0][0], ALPHA * r0a[0][1]);
            red2(op0 + 2*qq + 8, ALPHA * r0a[0][2], ALPHA * r0a[0][3]);
            red2(op1 + 2*qq,     ALPHA * r0a[1][0], ALPHA * r0a[1][1]);
            red2(op1 + 2*qq + 8, ALPHA * r0a[1][2], ALPHA * r0a[1][3]);
            if (qq == 0) {
                atomicAdd(&g_cnt[dn0], 1.0f);
                atomicAdd(&g_cnt[dn1], 1.0f);
            }
        }
        if (c == 15) {  // scatter out1
            int dns[2] = {((int*)(sm + DST_OFF))[r0], ((int*)(sm + DST_OFF))[r1]};
            int ers[2] = {r0, r1};
#pragma unroll
            for (int ei = 0; ei < 2; ei++) {
                float s1m[3];
#pragma unroll
                for (int m = 0; m < 3; m++) s1m[m] = sm[SH_OFF + ers[ei] * 4 + 1 + m];
                float* op = out + (size_t)dns[ei] * 64 + 16;
                float va[4][3];
#pragma unroll
                for (int s = 0; s < 4; s++)
#pragma unroll
                    for (int m = 0; m < 3; m++)
                        va[s][m] = ALPHA * fmaf(s1m[m], r2a[ei][s], r3a[ei][s][m]);
                red2(op + 6*qq + 0, va[0][0], va[0][1]);
                red2(op + 6*qq + 2, va[0][2], va[1][0]);
                red2(op + 6*qq + 4, va[1][1], va[1][2]);
                red2(op + 6*qq + 24, va[2][0], va[2][1]);
                red2(op + 6*qq + 26, va[2][2], va[3][0]);
                red2(op + 6*qq + 28, va[3][1], va[3][2]);
            }
        }
        if (c < 15) {   // no tail barrier on the last chunk
            cpwait0();
            __syncthreads();
        }
    }
}

// ---------------------------------------------------------------------------
extern "C" void kernel_launch(void* const* d_in, const int* in_sizes, int n_in,
                              void* d_out, int out_size) {
    const float* xfeat = (const float*)d_in[0];
    const float* eshv  = (const float*)d_in[1];
    const float* emb   = (const float*)d_in[2];
    const float* W1    = (const float*)d_in[3];
    const float* b1    = (const float*)d_in[4];
    const float* W2    = (const float*)d_in[5];
    const float* b2    = (const float*)d_in[6];
    const int*   src   = (const int*)d_in[7];
    const int*   dstp  = (const int*)d_in[8];
    float* out = (float*)d_out;

    cudaFuncSetAttribute(k_fused, cudaFuncAttributeMaxDynamicSharedMemorySize, SMEM_BYTES);

    k_prep<<<(NNODES * 16 + 255) / 256, 256>>>(W1, W2, (float4*)out);
    k_fused<<<E_TOTAL / EPB, 128, SMEM_BYTES>>>(xfeat, eshv, emb, b1, b2, src, dstp, out);
    k_norm<<<(NNODES * 16 + 255) / 256, 256>>>((float4*)out);
}